// round 8
// baseline (speedup 1.0000x reference)
#include <cuda_runtime.h>
#include <stdint.h>

#define TPB      256
#define NBLK     592               // 4 CTAs per SM * 148 SMs
#define KTOP     16
#define NC       (NBLK * KTOP)     // 9472
#define TILE_PTS 512
#define TILE_F4  768               // 512 pts * 6 floats / 4 = 12288 B
#define STAGES   4

typedef unsigned long long u64;

__device__ u64 g_cand[NC];

static __device__ __forceinline__ u64 make_key(float d2, int idx) {
    // d2 >= 0 -> float bits monotone. Larger key = larger d2; ties -> smaller
    // index (via ~idx), matching jax.lax.top_k ordering.
    return (((u64)__float_as_uint(d2)) << 32) | (unsigned)(~(unsigned)idx);
}

static __device__ __forceinline__ u64 warp_min16(u64 mykey, int lane) {
    u64 t = (lane < 16) ? mykey : 0xFFFFFFFFFFFFFFFFULL;
    #pragma unroll
    for (int off = 16; off; off >>= 1) {
        u64 o = __shfl_xor_sync(0xFFFFFFFFu, t, off);
        t = o < t ? o : t;
    }
    return t;
}

// Insert per-lane candidate kk into running top-16 (lanes 0..15 hold mykey).
// All branches warp-uniform; called by full warps only.
static __device__ __forceinline__ void warp_insert(u64 kk, u64& mykey,
                                                   u64& thresh, int lane) {
    const unsigned FULL = 0xFFFFFFFFu;
    unsigned bal = __ballot_sync(FULL, kk > thresh);
    while (bal) {
        int src = __ffs(bal) - 1;
        bal &= bal - 1;
        u64 ck = __shfl_sync(FULL, kk, src);
        if (ck > thresh) {   // warp-uniform recheck (thresh may have risen)
            unsigned who = __ballot_sync(FULL, (lane < 16) & (mykey == thresh));
            int ml = __ffs(who) - 1;
            if (lane == ml) mykey = ck;
            thresh = warp_min16(mykey, lane);
        }
    }
}

// Bitonic sort descending across lanes 0..15.
static __device__ __forceinline__ u64 sort16_desc(u64 v, int lane) {
    #pragma unroll
    for (int k = 2; k <= 16; k <<= 1) {
        #pragma unroll
        for (int j = k >> 1; j > 0; j >>= 1) {
            u64 o = __shfl_xor_sync(0xFFFFFFFFu, v, j);
            bool up = ((lane & k) == 0);
            bool lower = ((lane & j) == 0);
            v = ((lower == up) ? (v > o) : (v < o)) ? v : o;
        }
    }
    return v;
}

// Bitonic clean (descending) within an aligned 16-lane group; input c bitonic.
// MUST be executed by all 32 lanes of the warp (full-mask shfl inside).
static __device__ __forceinline__ u64 clean16_desc(u64 c, int id) {
    #pragma unroll
    for (int j = 8; j > 0; j >>= 1) {
        u64 o = __shfl_xor_sync(0xFFFFFFFFu, c, j);
        c = (((id & j) == 0) ? (c > o) : (c < o)) ? c : o;
    }
    return c;
}

static __device__ __forceinline__ void cp16(uint32_t s, const float4* g) {
    asm volatile("cp.async.cg.shared.global [%0], [%1], 16;\n"
                 :: "r"(s), "l"(g) : "memory");
}

__global__ void __launch_bounds__(TPB, 4) locse_scan(const float* __restrict__ P,
                                                     const int* __restrict__ iptr,
                                                     int n, int f4max, int ntiles) {
    __shared__ float4 s_buf[STAGES * TILE_F4];   // 49152 B
    const float4* __restrict__ P4 = (const float4*)P;
    int t = threadIdx.x, lane = t & 31, wid = t >> 5;
    uint32_t s_base = (uint32_t)__cvta_generic_to_shared(s_buf);

    int qi = *iptr;
    float pix = __ldg(P + (size_t)qi * 6 + 0);
    float piy = __ldg(P + (size_t)qi * 6 + 1);
    float piz = __ldg(P + (size_t)qi * 6 + 2);

    // prologue: issue STAGES-1 tiles (clamped addresses, one group each)
    #pragma unroll
    for (int s = 0; s < STAGES - 1; s++) {
        int tb = (blockIdx.x + s * NBLK) * TILE_F4;
        uint32_t sd = s_base + (uint32_t)(s * TILE_F4 + t) * 16u;
        cp16(sd,                 P4 + min(tb + t,           f4max - 1));
        cp16(sd + TPB * 16u,     P4 + min(tb + t + TPB,     f4max - 1));
        cp16(sd + 2 * TPB * 16u, P4 + min(tb + t + 2 * TPB, f4max - 1));
        asm volatile("cp.async.commit_group;\n" ::: "memory");
    }

    u64 mykey = 0ULL, thresh = 0ULL;
    int k = 0;
    for (int tile = blockIdx.x; tile < ntiles; tile += NBLK, k++) {
        asm volatile("cp.async.wait_group 2;\n" ::: "memory");
        __syncthreads();

        int stage = k & (STAGES - 1);
        const float* sf = (const float*)(s_buf + stage * TILE_F4);
        int p0 = tile * TILE_PTS + t;
        int p1 = p0 + TPB;
        float x0 = sf[6 * t + 0], y0 = sf[6 * t + 1], z0 = sf[6 * t + 2];
        int t2 = t + TPB;
        float x1 = sf[6 * t2 + 0], y1 = sf[6 * t2 + 1], z1 = sf[6 * t2 + 2];

        float dx = x0 - pix, dy = y0 - piy, dz = z0 - piz;
        u64 k0 = (p0 < n) ? make_key(dx * dx + dy * dy + dz * dz, p0) : 0ULL;
        dx = x1 - pix; dy = y1 - piy; dz = z1 - piz;
        u64 k1 = (p1 < n) ? make_key(dx * dx + dy * dy + dz * dz, p1) : 0ULL;

        warp_insert(k0, mykey, thresh, lane);
        warp_insert(k1, mykey, thresh, lane);

        __syncthreads();
        // refill the stage that tile (k+STAGES-1) maps to
        int ns = (k + STAGES - 1) & (STAGES - 1);
        int tb = (tile + (STAGES - 1) * NBLK) * TILE_F4;
        uint32_t sd = s_base + (uint32_t)(ns * TILE_F4 + t) * 16u;
        cp16(sd,                 P4 + min(tb + t,           f4max - 1));
        cp16(sd + TPB * 16u,     P4 + min(tb + t + TPB,     f4max - 1));
        cp16(sd + 2 * TPB * 16u, P4 + min(tb + t + 2 * TPB, f4max - 1));
        asm volatile("cp.async.commit_group;\n" ::: "memory");
    }

    // drain pending async copies before reusing smem
    asm volatile("cp.async.wait_group 0;\n" ::: "memory");
    __syncthreads();

    // per-warp sort -> tree merge 8 lists -> block top-16 descending
    // (guards here are warp-uniform: whole warps active -> full-mask shfl OK)
    u64* sm = (u64*)s_buf;
    u64 sk = sort16_desc((lane < 16) ? mykey : 0ULL, lane);
    if (lane < 16) sm[wid * 16 + lane] = sk;
    __syncthreads();
    #pragma unroll
    for (int nact = 4; nact >= 1; nact >>= 1) {
        u64 c = 0ULL;
        if (wid < nact) {
            int id = lane & 15;
            u64 a = sm[(2 * wid) * 16 + id];
            u64 b = sm[(2 * wid + 1) * 16 + (15 - id)];
            c = clean16_desc(a > b ? a : b, id);
        }
        __syncthreads();
        if (wid < nact && lane < 16) sm[wid * 16 + lane] = c;
        __syncthreads();
    }
    if (t < KTOP) g_cand[blockIdx.x * KTOP + t] = sm[t];
}

// 1024 threads: bitonic merge tree over 592 sorted descending 16-lists.
// FIX vs previous round: all threads execute clean16_desc (full-mask shfl);
// inactive units read clamped indices and only the WRITE is guarded.
__global__ void __launch_bounds__(1024) locse_final(const float* __restrict__ P,
                                                    const float* __restrict__ W,
                                                    const float* __restrict__ bb,
                                                    const int* __restrict__ iptr,
                                                    float* __restrict__ out) {
    __shared__ u64 sl[296 * KTOP];   // 37888 B
    int t = threadIdx.x;
    int unit = t >> 4;               // 64 merge units of 16 lanes
    int id = t & 15;

    // Level 1: 592 gmem lists -> 296 smem lists (5 rounds, unconditional shfl)
    #pragma unroll
    for (int u0 = 0; u0 < 296; u0 += 64) {
        int u = u0 + unit;
        bool act = u < 296;
        int ga = act ? (2 * u) * KTOP + id        : 0;
        int gb = act ? (2 * u + 1) * KTOP + (15 - id) : 0;
        u64 a = g_cand[ga];
        u64 b = g_cand[gb];
        u64 c = clean16_desc(a > b ? a : b, id);   // all 1024 threads execute
        if (act) sl[u * KTOP + id] = c;
    }
    __syncthreads();

    // In-place levels: 296 -> 148 -> 74 -> 37 -> 19 -> 10 -> 5 -> 3 -> 2 -> 1
    int m = 296;
    while (m > 1) {
        int h = (m + 1) >> 1;
        for (int u0 = 0; u0 < h; u0 += 64) {
            int u = u0 + unit;
            bool act = u < h;
            int ia = act ? (2 * u) * KTOP + id : 0;
            bool hasb = act && (2 * u + 1 < m);
            int ib = hasb ? (2 * u + 1) * KTOP + (15 - id) : 0;
            u64 a = sl[ia];
            u64 b = hasb ? sl[ib] : 0ULL;
            u64 c = clean16_desc(a > b ? a : b, id);  // unconditional
            __syncthreads();            // all reads done before any write
            if (act) sl[u * KTOP + id] = c;
            __syncthreads();
        }
        m = h;
    }

    if (t < KTOP) {
        u64 k = sl[t];
        int idx = (int)(~(unsigned)(k & 0xFFFFFFFFULL));
        int qi = *iptr;
        float pix = P[(size_t)qi * 6 + 0];
        float piy = P[(size_t)qi * 6 + 1];
        float piz = P[(size_t)qi * 6 + 2];
        float nx = P[(size_t)idx * 6 + 0];
        float ny = P[(size_t)idx * 6 + 1];
        float nz = P[(size_t)idx * 6 + 2];
        float dx = pix - nx, dy = piy - ny, dz = piz - nz;
        float dist = sqrtf(dx * dx + dy * dy + dz * dz);
        float feat[10] = {pix, piy, piz, nx, ny, nz, dx, dy, dz, dist};
        out[t * 6 + 0] = nx;
        out[t * 6 + 1] = ny;
        out[t * 6 + 2] = nz;
        #pragma unroll
        for (int j = 0; j < 3; j++) {
            float acc = bb[j];
            #pragma unroll
            for (int q = 0; q < 10; q++) acc += feat[q] * W[j * 10 + q];
            out[t * 6 + 3 + j] = acc;
        }
    }
}

extern "C" void kernel_launch(void* const* d_in, const int* in_sizes, int n_in,
                              void* d_out, int out_size) {
    const float* P  = (const float*)d_in[0];
    const float* W  = (const float*)d_in[1];
    const float* b  = (const float*)d_in[2];
    const int*   ip = (const int*)d_in[3];
    float* out = (float*)d_out;
    int n = in_sizes[0] / 6;
    int f4max = in_sizes[0] / 4;
    int ntiles = (n + TILE_PTS - 1) / TILE_PTS;

    locse_scan<<<NBLK, TPB>>>(P, ip, n, f4max, ntiles);
    locse_final<<<1, 1024>>>(P, W, b, ip, out);
}

// round 9
// speedup vs baseline: 4.6414x; 4.6414x over previous
#include <cuda_runtime.h>
#include <stdint.h>

#define TPB    256
#define NBLK   296                 // 2 CTAs/SM * 148 SMs
#define KTOP   16
#define PAIRS  3                   // point-pairs per thread per iteration

typedef unsigned long long u64;

__device__ u64 g_cand[NBLK * KTOP];
__device__ int g_done;             // zero at launch; last block resets it

static __device__ __forceinline__ u64 make_key(float d2, int idx) {
    // d2 >= 0 -> float bits monotone. Larger key = larger d2; ties -> smaller
    // index (via ~idx), matching jax.lax.top_k ordering.
    return (((u64)__float_as_uint(d2)) << 32) | (unsigned)(~(unsigned)idx);
}

static __device__ __forceinline__ u64 warp_min16(u64 mykey, int lane) {
    u64 t = (lane < 16) ? mykey : 0xFFFFFFFFFFFFFFFFULL;
    #pragma unroll
    for (int off = 16; off; off >>= 1) {
        u64 o = __shfl_xor_sync(0xFFFFFFFFu, t, off);
        t = o < t ? o : t;
    }
    return t;
}

// Insert per-lane candidate kk into running top-16 (lanes 0..15 hold mykey).
// Warp-uniform control flow; full warp always participates.
static __device__ __forceinline__ void warp_insert(u64 kk, u64& mykey,
                                                   u64& thresh, int lane) {
    const unsigned FULL = 0xFFFFFFFFu;
    unsigned bal = __ballot_sync(FULL, kk > thresh);
    while (bal) {
        int src = __ffs(bal) - 1;
        bal &= bal - 1;
        u64 ck = __shfl_sync(FULL, kk, src);
        if (ck > thresh) {   // warp-uniform recheck (thresh may have risen)
            unsigned who = __ballot_sync(FULL, (lane < 16) & (mykey == thresh));
            int ml = __ffs(who) - 1;
            if (lane == ml) mykey = ck;
            thresh = warp_min16(mykey, lane);
        }
    }
}

// Bitonic sort descending across lanes 0..15 (full warp executes).
static __device__ __forceinline__ u64 sort16_desc(u64 v, int lane) {
    #pragma unroll
    for (int k = 2; k <= 16; k <<= 1) {
        #pragma unroll
        for (int j = k >> 1; j > 0; j >>= 1) {
            u64 o = __shfl_xor_sync(0xFFFFFFFFu, v, j);
            bool up = ((lane & k) == 0);
            bool lower = ((lane & j) == 0);
            v = ((lower == up) ? (v > o) : (v < o)) ? v : o;
        }
    }
    return v;
}

// Bitonic clean (descending) in aligned 16-lane groups; input bitonic.
// MUST be executed by all 32 lanes (full-mask shfl inside).
static __device__ __forceinline__ u64 clean16_desc(u64 c, int id) {
    #pragma unroll
    for (int j = 8; j > 0; j >>= 1) {
        u64 o = __shfl_xor_sync(0xFFFFFFFFu, c, j);
        c = (((id & j) == 0) ? (c > o) : (c < o)) ? c : o;
    }
    return c;
}

static __device__ __forceinline__ u64 umax64(u64 a, u64 b) { return a > b ? a : b; }

__global__ void __launch_bounds__(TPB, 2)
locse_fused(const float* __restrict__ P, const float* __restrict__ W,
            const float* __restrict__ bb, const int* __restrict__ iptr,
            float* __restrict__ out, int n, int niter) {
    const unsigned FULL = 0xFFFFFFFFu;
    const float4* __restrict__ P4 = (const float4*)P;
    int t = threadIdx.x, lane = t & 31, wid = t >> 5;
    const int T = NBLK * TPB;                 // total threads
    const int NP = n >> 1;                    // point pairs
    const int g = blockIdx.x * TPB + t;

    int qi = *iptr;
    float pix = __ldg(P + (size_t)qi * 6 + 0);
    float piy = __ldg(P + (size_t)qi * 6 + 1);
    float piz = __ldg(P + (size_t)qi * 6 + 2);

    // ---- barrier-free register-pipelined scan ----
    float4 buf[2][3 * PAIRS];
    #pragma unroll
    for (int j = 0; j < PAIRS; j++) {
        int q = g + j * T; q = min(q, NP - 1);
        size_t b = (size_t)q * 3;
        buf[0][3 * j + 0] = __ldg(P4 + b + 0);
        buf[0][3 * j + 1] = __ldg(P4 + b + 1);
        buf[0][3 * j + 2] = __ldg(P4 + b + 2);
    }

    u64 mykey = 0ULL, thresh = 0ULL;

    for (int it = 0; it < niter; it++) {
        int cb = it & 1;
        // prefetch next iteration (clamped, unconditional -> batched LDG.128)
        #pragma unroll
        for (int j = 0; j < PAIRS; j++) {
            int q = g + (PAIRS * (it + 1) + j) * T; q = min(q, NP - 1);
            size_t b = (size_t)q * 3;
            buf[cb ^ 1][3 * j + 0] = __ldg(P4 + b + 0);
            buf[cb ^ 1][3 * j + 1] = __ldg(P4 + b + 1);
            buf[cb ^ 1][3 * j + 2] = __ldg(P4 + b + 2);
        }

        u64 k[2 * PAIRS];
        #pragma unroll
        for (int j = 0; j < PAIRS; j++) {
            int q = g + (PAIRS * it + j) * T;
            bool v = q < NP;
            float4 A = buf[cb][3 * j + 0];
            float4 B = buf[cb][3 * j + 1];
            float4 C = buf[cb][3 * j + 2];
            float dx = A.x - pix, dy = A.y - piy, dz = A.z - piz;
            k[2 * j] = v ? make_key(dx * dx + dy * dy + dz * dz, 2 * q) : 0ULL;
            dx = B.z - pix; dy = B.w - piy; dz = C.x - piz;
            k[2 * j + 1] = v ? make_key(dx * dx + dy * dy + dz * dz, 2 * q + 1) : 0ULL;
        }

        // fast-path: one ballot on the per-thread max
        u64 m = k[0];
        #pragma unroll
        for (int j = 1; j < 2 * PAIRS; j++) m = umax64(m, k[j]);
        if (__ballot_sync(FULL, m > thresh)) {        // warp-uniform branch
            #pragma unroll
            for (int j = 0; j < 2 * PAIRS; j++)
                warp_insert(k[j], mykey, thresh, lane);
        }
    }

    // ---- block reduce: 8 warps -> sorted descending top-16 ----
    __shared__ u64 sm[8 * KTOP];
    u64 sk = sort16_desc((lane < 16) ? mykey : 0ULL, lane);
    if (lane < 16) sm[wid * 16 + lane] = sk;
    __syncthreads();
    #pragma unroll
    for (int nact = 4; nact >= 1; nact >>= 1) {
        u64 c = 0ULL;
        if (wid < nact) {                   // warp-uniform guard
            int id = lane & 15;
            u64 a = sm[(2 * wid) * 16 + id];
            u64 b = sm[(2 * wid + 1) * 16 + (15 - id)];
            c = clean16_desc(umax64(a, b), id);
        }
        __syncthreads();
        if (wid < nact && lane < 16) sm[wid * 16 + lane] = c;
        __syncthreads();
    }
    if (t < KTOP) g_cand[blockIdx.x * KTOP + t] = sm[t];

    // ---- last-block final merge + epilogue ----
    __shared__ int s_last;
    __threadfence();
    if (t == 0) {
        int old = atomicAdd(&g_done, 1);
        s_last = (old == NBLK - 1);
        if (s_last) g_done = 0;             // reset for next graph replay
    }
    __syncthreads();
    if (!s_last) return;
    __threadfence();

    __shared__ u64 sl[148 * KTOP];          // 18944 B
    int unit = t >> 4;                      // 16 merge units of 16 lanes
    int id = t & 15;

    // Level 1: 296 gmem lists -> 148 smem lists (volatile: cross-SM data)
    for (int u0 = 0; u0 < 148; u0 += 16) {
        int u = u0 + unit;
        bool act = u < 148;
        int ga = act ? (2 * u) * KTOP + id : 0;
        int gb = act ? (2 * u + 1) * KTOP + (15 - id) : 0;
        u64 a = *(volatile u64*)&g_cand[ga];
        u64 b = *(volatile u64*)&g_cand[gb];
        u64 c = clean16_desc(umax64(a, b), id);   // all 256 threads execute
        if (act) sl[u * KTOP + id] = c;
    }
    __syncthreads();

    // In-place: 148 -> 74 -> 37 -> 19 -> 10 -> 5 -> 3 -> 2 -> 1
    int mm = 148;
    while (mm > 1) {
        int h = (mm + 1) >> 1;
        for (int u0 = 0; u0 < h; u0 += 16) {
            int u = u0 + unit;
            bool act = u < h;
            int ia = act ? (2 * u) * KTOP + id : 0;
            bool hasb = act && (2 * u + 1 < mm);
            int ib = hasb ? (2 * u + 1) * KTOP + (15 - id) : 0;
            u64 a = sl[ia];
            u64 b = hasb ? sl[ib] : 0ULL;
            u64 c = clean16_desc(umax64(a, b), id);   // unconditional shfl
            __syncthreads();                // all reads before any write
            if (act) sl[u * KTOP + id] = c;
            __syncthreads();
        }
        mm = h;
    }

    if (t < KTOP) {
        u64 kk = sl[t];
        int idx = (int)(~(unsigned)(kk & 0xFFFFFFFFULL));
        float nx = P[(size_t)idx * 6 + 0];
        float ny = P[(size_t)idx * 6 + 1];
        float nz = P[(size_t)idx * 6 + 2];
        float dx = pix - nx, dy = piy - ny, dz = piz - nz;
        float dist = sqrtf(dx * dx + dy * dy + dz * dz);
        float feat[10] = {pix, piy, piz, nx, ny, nz, dx, dy, dz, dist};
        out[t * 6 + 0] = nx;
        out[t * 6 + 1] = ny;
        out[t * 6 + 2] = nz;
        #pragma unroll
        for (int j = 0; j < 3; j++) {
            float acc = bb[j];
            #pragma unroll
            for (int q = 0; q < 10; q++) acc += feat[q] * W[j * 10 + q];
            out[t * 6 + 3 + j] = acc;
        }
    }
}

extern "C" void kernel_launch(void* const* d_in, const int* in_sizes, int n_in,
                              void* d_out, int out_size) {
    const float* P  = (const float*)d_in[0];
    const float* W  = (const float*)d_in[1];
    const float* b  = (const float*)d_in[2];
    const int*   ip = (const int*)d_in[3];
    float* out = (float*)d_out;
    int n = in_sizes[0] / 6;
    int NP = n >> 1;
    int T = NBLK * TPB;
    int niter = (NP + PAIRS * T - 1) / (PAIRS * T);

    locse_fused<<<NBLK, TPB>>>(P, W, b, ip, out, n, niter);
}